// round 15
// baseline (speedup 1.0000x reference)
#include <cuda_runtime.h>
#include <math.h>
#include <stdint.h>

#define BB 64
#define TT 512
#define DD 512
#define MM (BB*TT)   // 32768

typedef unsigned long long u64;

// Scratch for the precomputed projections (192 MB total)
__device__ float g_ev[MM*DD];
__device__ float g_leak[MM*DD];
__device__ float g_write[MM*DD];

// ---- packed fp32x2 helpers (Blackwell f32x2 pipe; exact IEEE fp32) ----
__device__ __forceinline__ u64 pack2(float lo, float hi) {
    u64 r; asm("mov.b64 %0, {%1, %2};" : "=l"(r) : "f"(lo), "f"(hi)); return r;
}
__device__ __forceinline__ void unpack2(u64 v, float& lo, float& hi) {
    asm("mov.b64 {%0, %1}, %2;" : "=f"(lo), "=f"(hi) : "l"(v));
}
__device__ __forceinline__ u64 ffma2(u64 a, u64 b, u64 c) {
    u64 d; asm("fma.rn.f32x2 %0, %1, %2, %3;" : "=l"(d) : "l"(a), "l"(b), "l"(c));
    return d;
}

// fast tanh: sign-safe, __expf-based (MUFU path), ~1e-6 rel error
__device__ __forceinline__ float fast_tanh(float x) {
    const float a = fabsf(x);
    const float t = __expf(-2.0f * a);
    const float r = __fdividef(1.0f - t, 1.0f + t);
    return copysignf(r, x);
}

// ---------------------------------------------------------------------------
// Kernel A (R12-proven inner loop), FUSED: blockIdx.z selects the projection
// (0: We/be no act; 1: Wl/bl sigmoid; 2: Ww/bw sigmoid). One 3072-CTA grid
// instead of 3x 1024 — saves two partial-wave tails + launch gaps.
// ---------------------------------------------------------------------------
__global__ __launch_bounds__(256, 2)
void proj_gemm_fused(const float* __restrict__ X,
                     const float* __restrict__ We, const float* __restrict__ be,
                     const float* __restrict__ Wl, const float* __restrict__ bl,
                     const float* __restrict__ Ww, const float* __restrict__ bw,
                     float* __restrict__ Ye, float* __restrict__ Yl,
                     float* __restrict__ Yw)
{
    constexpr int BM = 128, BN = 128, BK = 16;
    __shared__ __align__(16) float As[BK*BM];   // [k][m]
    __shared__ __align__(16) float Bs[BK*BN];   // [k][n]

    const int z = blockIdx.z;
    const float* W    = (z == 0) ? We : (z == 1) ? Wl : Ww;
    const float* bias = (z == 0) ? be : (z == 1) ? bl : bw;
    float* Y          = (z == 0) ? Ye : (z == 1) ? Yl : Yw;
    const bool act    = (z != 0);

    const int tid = threadIdx.x;
    const int m0 = blockIdx.x * BM;
    const int n0 = blockIdx.y * BN;
    const int tx = tid & 15;
    const int ty = tid >> 4;

    const int arow = tid >> 2;
    const int acol = (tid & 3) * 4;
    const int brow = tid >> 5;
    const int bcol = (tid & 31) * 4;

    u64 acc2[8][4];
    #pragma unroll
    for (int i = 0; i < 8; i++)
        #pragma unroll
        for (int j = 0; j < 4; j++) acc2[i][j] = 0ULL;

    {
        float4 a0 = *(const float4*)&X[(size_t)(m0 + arow     ) * DD + acol];
        float4 a1 = *(const float4*)&X[(size_t)(m0 + arow + 64) * DD + acol];
        float4 b0 = *(const float4*)&W[(size_t)(brow    ) * DD + n0 + bcol];
        float4 b1 = *(const float4*)&W[(size_t)(brow + 8) * DD + n0 + bcol];
        As[(acol + 0) * BM + arow] = a0.x;
        As[(acol + 1) * BM + arow] = a0.y;
        As[(acol + 2) * BM + arow] = a0.z;
        As[(acol + 3) * BM + arow] = a0.w;
        As[(acol + 0) * BM + arow + 64] = a1.x;
        As[(acol + 1) * BM + arow + 64] = a1.y;
        As[(acol + 2) * BM + arow + 64] = a1.z;
        As[(acol + 3) * BM + arow + 64] = a1.w;
        *(float4*)&Bs[(brow    ) * BN + bcol] = b0;
        *(float4*)&Bs[(brow + 8) * BN + bcol] = b1;
    }
    __syncthreads();

    for (int k0 = 0; k0 < DD; k0 += BK) {
        const bool more = (k0 + BK < DD);
        float4 na0, na1, nb0, nb1;
        if (more) {
            na0 = *(const float4*)&X[(size_t)(m0 + arow     ) * DD + k0 + BK + acol];
            na1 = *(const float4*)&X[(size_t)(m0 + arow + 64) * DD + k0 + BK + acol];
            nb0 = *(const float4*)&W[(size_t)(k0 + BK + brow    ) * DD + n0 + bcol];
            nb1 = *(const float4*)&W[(size_t)(k0 + BK + brow + 8) * DD + n0 + bcol];
        }

        #pragma unroll
        for (int kk = 0; kk < BK; kk++) {
            float4 aA = *(const float4*)&As[kk * BM + ty * 8];
            float4 aB = *(const float4*)&As[kk * BM + ty * 8 + 4];
            ulonglong2 bp0 = *(const ulonglong2*)&Bs[kk * BN + tx * 8];
            ulonglong2 bp1 = *(const ulonglong2*)&Bs[kk * BN + tx * 8 + 4];
            u64 b2[4] = { bp0.x, bp0.y, bp1.x, bp1.y };
            float av[8] = { aA.x, aA.y, aA.z, aA.w, aB.x, aB.y, aB.z, aB.w };
            #pragma unroll
            for (int i = 0; i < 8; i++) {
                const u64 ap = pack2(av[i], av[i]);
                #pragma unroll
                for (int j = 0; j < 4; j++)
                    acc2[i][j] = ffma2(ap, b2[j], acc2[i][j]);
            }
        }

        if (more) {
            __syncthreads();
            As[(acol + 0) * BM + arow] = na0.x;
            As[(acol + 1) * BM + arow] = na0.y;
            As[(acol + 2) * BM + arow] = na0.z;
            As[(acol + 3) * BM + arow] = na0.w;
            As[(acol + 0) * BM + arow + 64] = na1.x;
            As[(acol + 1) * BM + arow + 64] = na1.y;
            As[(acol + 2) * BM + arow + 64] = na1.z;
            As[(acol + 3) * BM + arow + 64] = na1.w;
            *(float4*)&Bs[(brow    ) * BN + bcol] = nb0;
            *(float4*)&Bs[(brow + 8) * BN + bcol] = nb1;
            __syncthreads();
        }
    }

    #pragma unroll
    for (int i = 0; i < 8; i++) {
        const int m = m0 + ty * 8 + i;
        #pragma unroll
        for (int j = 0; j < 4; j++) {
            float lo, hi;
            unpack2(acc2[i][j], lo, hi);
            const int n = n0 + tx * 8 + 2 * j;
            float v0 = lo + bias[n];
            float v1 = hi + bias[n + 1];
            if (act) {
                v0 = 1.0f / (1.0f + expf(-v0));
                v1 = 1.0f / (1.0f + expf(-v1));
            }
            Y[(size_t)m * DD + n]     = v0;
            Y[(size_t)m * DD + n + 1] = v1;
        }
    }
}

// ---------------------------------------------------------------------------
// Kernel B: cluster-resident scan — EXACT R12 structure (w in registers,
// per-source slot mbarriers, distributed senders) with ONE change:
// the reducer/sender role moves to warps 8..15 (tid >= 256). The warp
// arbiter is highest-wid-first, so the serial critical chain (reduce ->
// gates -> send) now has priority over the low-wid warps spinning in
// try_wait, instead of being preempted by them.
// ---------------------------------------------------------------------------
#define CLUSTER_C 8
#define NCLUST 16
#define BPC 4
#define DLOC 64
#define SCAN_THREADS 512
#define SLICE_BYTES (BPC*DLOC*4)             // 1024

__global__ __launch_bounds__(SCAN_THREADS, 1) __cluster_dims__(CLUSTER_C, 1, 1)
void scan_cluster_kernel(const float* __restrict__ Wp, const float* __restrict__ bp,
                         float* __restrict__ out)
{
    __shared__ __align__(16) float bel[2][CLUSTER_C][BPC][DLOC];  // 16 KB
    __shared__ __align__(16) float sp[BPC][8][DLOC];              // 8 KB
    __shared__ __align__(16) float stage[2][BPC][DLOC];           // 2 KB
    __shared__ __align__(8)  u64  sb[2][CLUSTER_C];               // slot barriers

    const int tid     = threadIdx.x;
    const int d_local = tid & 63;
    const int ksec    = tid >> 6;        // 0..7 == source rank this thread reads
    const int kbase   = ksec * 64;

    uint32_t rank;
    asm("mov.u32 %0, %%cluster_ctarank;" : "=r"(rank));
    const int cluster_id = blockIdx.x / CLUSTER_C;
    const int b0    = cluster_id * BPC;
    const int dglob = (int)rank * DLOC + d_local;

    // ---- Persistent Wp slice in registers ----
    float w[64];
    #pragma unroll
    for (int j = 0; j < 64; j++)
        w[j] = Wp[(size_t)(kbase + j) * DD + dglob];

    // ---- init belief buffer 0 + slot mbarriers ----
    for (int i = tid; i < CLUSTER_C * BPC * DLOC; i += SCAN_THREADS)
        (&bel[0][0][0][0])[i] = 0.0f;
    const uint32_t sb_base = (uint32_t)__cvta_generic_to_shared(&sb[0][0]);
    if (tid < 2 * CLUSTER_C) {
        const uint32_t mb = sb_base + tid * 8;
        asm volatile("mbarrier.init.shared.b64 [%0], 1;" :: "r"(mb) : "memory");
    }
    __syncthreads();

    // this thread's wait barrier addresses (slot = ksec), per buffer
    const uint32_t my_mb[2] = { sb_base + (uint32_t)ksec * 8,
                                sb_base + (uint32_t)(CLUSTER_C + ksec) * 8 };

    // ---- reducer state: threads 256..511 (warps 8..15, HIGH wid priority) ----
    const int  rb     = ksec & 3;        // batch index (same mapping both halves)
    const bool is_red = (tid >= 256);
    float bel_prev = 0.0f;
    float bpv = 0.0f;
    size_t io_base = 0;
    if (is_red) {
        bpv = bp[dglob];
        io_base = ((size_t)(b0 + rb) * TT) * DD + dglob;
    }

    // one cluster sync: all CTAs' bel[0] + barriers ready before any traffic
    asm volatile("barrier.cluster.arrive.aligned;" ::: "memory");
    asm volatile("barrier.cluster.wait.aligned;"   ::: "memory");

    int ph0 = 0, ph1 = 0;

    for (int t = 0; t < TT; t++) {
        const int cur = t & 1;
        const int nxt = cur ^ 1;

        // gate prefetch BEFORE the wait: DRAM latency hides under wait+matvec
        float evv = 0.f, lkv = 0.f, wrv = 0.f;
        if (is_red) {
            const size_t idx = io_base + (size_t)t * DD;
            evv = g_ev[idx];
            lkv = g_leak[idx];
            wrv = g_write[idx];
        }

        // ---- wait ONLY for my source slot (slice ksec of phase cur) ----
        if (t > 0) {
            const uint32_t mb = my_mb[cur];
            const int ph = cur ? ph1 : ph0;
            uint32_t done;
            asm volatile(
                "{\n\t.reg .pred p;\n\t"
                "mbarrier.try_wait.parity.acquire.cta.shared::cta.b64 p, [%1], %2;\n\t"
                "selp.b32 %0, 1, 0, p;\n\t}"
                : "=r"(done) : "r"(mb), "r"(ph) : "memory");
            if (!done) {
                asm volatile(
                    "{\n\t.reg .pred P1;\n\t"
                    "W%=:\n\t"
                    "mbarrier.try_wait.parity.acquire.cta.shared::cta.b64 P1, [%0], %1, 0x989680;\n\t"
                    "@P1 bra.uni D%=;\n\t"
                    "bra.uni W%=;\n\t"
                    "D%=:\n\t}"
                    :: "r"(mb), "r"(ph) : "memory");
            }
        }
        if (t > 0) { if (cur) ph1 ^= 1; else ph0 ^= 1; }

        // ---- matvec partials: 4-batch interleave (R8/R12-proven) ----
        const float4* bl0 = (const float4*)&bel[cur][ksec][0][0];
        const float4* bl1 = (const float4*)&bel[cur][ksec][1][0];
        const float4* bl2 = (const float4*)&bel[cur][ksec][2][0];
        const float4* bl3 = (const float4*)&bel[cur][ksec][3][0];
        float a0 = 0.f, a1 = 0.f, a2 = 0.f, a3 = 0.f;
        #pragma unroll
        for (int j4 = 0; j4 < 16; j4++) {
            const float4 v0 = bl0[j4];
            const float4 v1 = bl1[j4];
            const float4 v2 = bl2[j4];
            const float4 v3 = bl3[j4];
            a0 = fmaf(v0.x, w[4*j4+0], a0);
            a0 = fmaf(v0.y, w[4*j4+1], a0);
            a0 = fmaf(v0.z, w[4*j4+2], a0);
            a0 = fmaf(v0.w, w[4*j4+3], a0);
            a1 = fmaf(v1.x, w[4*j4+0], a1);
            a1 = fmaf(v1.y, w[4*j4+1], a1);
            a1 = fmaf(v1.z, w[4*j4+2], a1);
            a1 = fmaf(v1.w, w[4*j4+3], a1);
            a2 = fmaf(v2.x, w[4*j4+0], a2);
            a2 = fmaf(v2.y, w[4*j4+1], a2);
            a2 = fmaf(v2.z, w[4*j4+2], a2);
            a2 = fmaf(v2.w, w[4*j4+3], a2);
            a3 = fmaf(v3.x, w[4*j4+0], a3);
            a3 = fmaf(v3.y, w[4*j4+1], a3);
            a3 = fmaf(v3.z, w[4*j4+2], a3);
            a3 = fmaf(v3.w, w[4*j4+3], a3);
        }
        sp[0][ksec][d_local] = a0;
        sp[1][ksec][d_local] = a1;
        sp[2][ksec][d_local] = a2;
        sp[3][ksec][d_local] = a3;
        __syncthreads();   // sync#1: all partials visible to reducers

        if (is_red) {
            // ---- reduce + gates -> staging ----
            float s = 0.f;
            #pragma unroll
            for (int q = 0; q < 8; q++) s += sp[rb][q][d_local];
            const float cand = fast_tanh(s + bpv + evv);
            const float nb   = lkv * bel_prev + wrv * cand;
            bel_prev = nb;
            stage[cur][rb][d_local] = nb;

            // sync#2: named barrier over the 256 reducer threads (warps 8-15)
            asm volatile("bar.sync 1, 256;" ::: "memory");

            if (t < TT - 1) {
                // arm my local slot barriers for phase nxt: slot q expects 1KB
                if (tid < 256 + CLUSTER_C) {     // tid 256..263
                    const int slot = tid - 256;
                    const uint32_t mb_a =
                        sb_base + (uint32_t)(nxt * CLUSTER_C + slot) * 8;
                    asm volatile(
                        "mbarrier.arrive.expect_tx.shared.b64 _, [%0], %1;"
                        :: "r"(mb_a), "r"((uint32_t)SLICE_BYTES) : "memory");
                }
                // reducer warp (8+w)'s lane 0 sends MY slice to peer w,
                // tagged to the peer's slot barrier [nxt][my rank]
                if ((tid & 31) == 0) {
                    const int peer = (tid >> 5) - 8;   // 0..7
                    asm volatile("fence.proxy.async.shared::cta;" ::: "memory");
                    const uint32_t mb_l =
                        sb_base + (uint32_t)(nxt * CLUSTER_C + (int)rank) * 8;
                    const uint32_t src =
                        (uint32_t)__cvta_generic_to_shared(&stage[cur][0][0]);
                    const uint32_t dst_l =
                        (uint32_t)__cvta_generic_to_shared(&bel[nxt][rank][0][0]);
                    uint32_t dst_r, mb_r;
                    asm("mapa.shared::cluster.u32 %0, %1, %2;"
                        : "=r"(dst_r) : "r"(dst_l), "r"(peer));
                    asm("mapa.shared::cluster.u32 %0, %1, %2;"
                        : "=r"(mb_r) : "r"(mb_l), "r"(peer));
                    asm volatile(
                        "cp.async.bulk.shared::cluster.shared::cta.mbarrier::complete_tx::bytes "
                        "[%0], [%1], %2, [%3];"
                        :: "r"(dst_r), "r"(src), "r"((uint32_t)SLICE_BYTES), "r"(mb_r)
                        : "memory");
                }
            }
            // off-chain global store
            out[io_base + (size_t)t * DD] = nb;
        }
        // warps 0..7 fall through to their next slot wait; their sp
        // overwrite at t+1 is ordered by wait(t+1) <= senders' copies(t)
        // <= bar.sync1(t) <= reducers' sp reads(t).
    }
}

// ---------------------------------------------------------------------------
// Launch
// ---------------------------------------------------------------------------
extern "C" void kernel_launch(void* const* d_in, const int* in_sizes, int n_in,
                              void* d_out, int out_size)
{
    const float* evseq = (const float*)d_in[0];
    const float* We    = (const float*)d_in[1];
    const float* be    = (const float*)d_in[2];
    const float* Wp    = (const float*)d_in[3];
    const float* bp    = (const float*)d_in[4];
    const float* Wl    = (const float*)d_in[5];
    const float* bl    = (const float*)d_in[6];
    const float* Ww    = (const float*)d_in[7];
    const float* bw    = (const float*)d_in[8];
    float* out = (float*)d_out;

    float *p_ev, *p_leak, *p_write;
    cudaGetSymbolAddress((void**)&p_ev,    g_ev);
    cudaGetSymbolAddress((void**)&p_leak,  g_leak);
    cudaGetSymbolAddress((void**)&p_write, g_write);

    dim3 grid(MM / 128, DD / 128, 3);
    dim3 blk(256);
    proj_gemm_fused<<<grid, blk>>>(evseq, We, be, Wl, bl, Ww, bw,
                                   p_ev, p_leak, p_write);

    scan_cluster_kernel<<<NCLUST * CLUSTER_C, SCAN_THREADS>>>(Wp, bp, out);
}

// round 16
// speedup vs baseline: 1.4668x; 1.4668x over previous
#include <cuda_runtime.h>
#include <math.h>
#include <stdint.h>

#define BB 64
#define TT 512
#define DD 512
#define MM (BB*TT)   // 32768

typedef unsigned long long u64;

// Scratch for the precomputed projections (192 MB total)
__device__ float g_ev[MM*DD];
__device__ float g_leak[MM*DD];
__device__ float g_write[MM*DD];

// ---- packed fp32x2 helpers (Blackwell f32x2 pipe; exact IEEE fp32) ----
__device__ __forceinline__ u64 pack2(float lo, float hi) {
    u64 r; asm("mov.b64 %0, {%1, %2};" : "=l"(r) : "f"(lo), "f"(hi)); return r;
}
__device__ __forceinline__ void unpack2(u64 v, float& lo, float& hi) {
    asm("mov.b64 {%0, %1}, %2;" : "=f"(lo), "=f"(hi) : "l"(v));
}
__device__ __forceinline__ u64 ffma2(u64 a, u64 b, u64 c) {
    u64 d; asm("fma.rn.f32x2 %0, %1, %2, %3;" : "=l"(d) : "l"(a), "l"(b), "l"(c));
    return d;
}

// fast tanh: sign-safe, __expf-based (MUFU path), ~1e-6 rel error
__device__ __forceinline__ float fast_tanh(float x) {
    const float a = fabsf(x);
    const float t = __expf(-2.0f * a);
    const float r = __fdividef(1.0f - t, 1.0f + t);
    return copysignf(r, x);
}

// ---------------------------------------------------------------------------
// Kernel A (R12-proven): Y[m][n] = act( sum_k X[m][k]*W[k][n] + b[n] )
// BM=128, BN=128, BK=16, 256 threads, 8x8 tile, f32x2 inner loop,
// k-major As, register-prefetch double buffering. Three separate launches
// (fusion measured slower). Sigmoid via __expf (MUFU).
// ---------------------------------------------------------------------------
template<int ACT>
__global__ __launch_bounds__(256, 2)
void proj_gemm(const float* __restrict__ X, const float* __restrict__ W,
               const float* __restrict__ bias, float* __restrict__ Y)
{
    constexpr int BM = 128, BN = 128, BK = 16;
    __shared__ __align__(16) float As[BK*BM];   // [k][m]
    __shared__ __align__(16) float Bs[BK*BN];   // [k][n]

    const int tid = threadIdx.x;
    const int m0 = blockIdx.x * BM;
    const int n0 = blockIdx.y * BN;
    const int tx = tid & 15;
    const int ty = tid >> 4;

    const int arow = tid >> 2;
    const int acol = (tid & 3) * 4;
    const int brow = tid >> 5;
    const int bcol = (tid & 31) * 4;

    u64 acc2[8][4];
    #pragma unroll
    for (int i = 0; i < 8; i++)
        #pragma unroll
        for (int j = 0; j < 4; j++) acc2[i][j] = 0ULL;

    {
        float4 a0 = *(const float4*)&X[(size_t)(m0 + arow     ) * DD + acol];
        float4 a1 = *(const float4*)&X[(size_t)(m0 + arow + 64) * DD + acol];
        float4 b0 = *(const float4*)&W[(size_t)(brow    ) * DD + n0 + bcol];
        float4 b1 = *(const float4*)&W[(size_t)(brow + 8) * DD + n0 + bcol];
        As[(acol + 0) * BM + arow] = a0.x;
        As[(acol + 1) * BM + arow] = a0.y;
        As[(acol + 2) * BM + arow] = a0.z;
        As[(acol + 3) * BM + arow] = a0.w;
        As[(acol + 0) * BM + arow + 64] = a1.x;
        As[(acol + 1) * BM + arow + 64] = a1.y;
        As[(acol + 2) * BM + arow + 64] = a1.z;
        As[(acol + 3) * BM + arow + 64] = a1.w;
        *(float4*)&Bs[(brow    ) * BN + bcol] = b0;
        *(float4*)&Bs[(brow + 8) * BN + bcol] = b1;
    }
    __syncthreads();

    for (int k0 = 0; k0 < DD; k0 += BK) {
        const bool more = (k0 + BK < DD);
        float4 na0, na1, nb0, nb1;
        if (more) {
            na0 = *(const float4*)&X[(size_t)(m0 + arow     ) * DD + k0 + BK + acol];
            na1 = *(const float4*)&X[(size_t)(m0 + arow + 64) * DD + k0 + BK + acol];
            nb0 = *(const float4*)&W[(size_t)(k0 + BK + brow    ) * DD + n0 + bcol];
            nb1 = *(const float4*)&W[(size_t)(k0 + BK + brow + 8) * DD + n0 + bcol];
        }

        #pragma unroll
        for (int kk = 0; kk < BK; kk++) {
            float4 aA = *(const float4*)&As[kk * BM + ty * 8];
            float4 aB = *(const float4*)&As[kk * BM + ty * 8 + 4];
            ulonglong2 bp0 = *(const ulonglong2*)&Bs[kk * BN + tx * 8];
            ulonglong2 bp1 = *(const ulonglong2*)&Bs[kk * BN + tx * 8 + 4];
            u64 b2[4] = { bp0.x, bp0.y, bp1.x, bp1.y };
            float av[8] = { aA.x, aA.y, aA.z, aA.w, aB.x, aB.y, aB.z, aB.w };
            #pragma unroll
            for (int i = 0; i < 8; i++) {
                const u64 ap = pack2(av[i], av[i]);
                #pragma unroll
                for (int j = 0; j < 4; j++)
                    acc2[i][j] = ffma2(ap, b2[j], acc2[i][j]);
            }
        }

        if (more) {
            __syncthreads();
            As[(acol + 0) * BM + arow] = na0.x;
            As[(acol + 1) * BM + arow] = na0.y;
            As[(acol + 2) * BM + arow] = na0.z;
            As[(acol + 3) * BM + arow] = na0.w;
            As[(acol + 0) * BM + arow + 64] = na1.x;
            As[(acol + 1) * BM + arow + 64] = na1.y;
            As[(acol + 2) * BM + arow + 64] = na1.z;
            As[(acol + 3) * BM + arow + 64] = na1.w;
            *(float4*)&Bs[(brow    ) * BN + bcol] = nb0;
            *(float4*)&Bs[(brow + 8) * BN + bcol] = nb1;
            __syncthreads();
        }
    }

    #pragma unroll
    for (int i = 0; i < 8; i++) {
        const int m = m0 + ty * 8 + i;
        #pragma unroll
        for (int j = 0; j < 4; j++) {
            float lo, hi;
            unpack2(acc2[i][j], lo, hi);
            const int n = n0 + tx * 8 + 2 * j;
            float v0 = lo + bias[n];
            float v1 = hi + bias[n + 1];
            if (ACT == 1) {
                v0 = __fdividef(1.0f, 1.0f + __expf(-v0));
                v1 = __fdividef(1.0f, 1.0f + __expf(-v1));
            }
            Y[(size_t)m * DD + n]     = v0;
            Y[(size_t)m * DD + n + 1] = v1;
        }
    }
}

// ---------------------------------------------------------------------------
// Kernel B: cluster-resident scan — EXACT R12 winner structure:
//   w in registers, 4-batch interleaved scalar matvec, per-source slot
//   mbarriers, reducers/senders = warps 0..7 (tid < 256), fast_tanh.
//   Only change: 'out' STG issued before bar.sync#2 (off the chain).
// ---------------------------------------------------------------------------
#define CLUSTER_C 8
#define NCLUST 16
#define BPC 4
#define DLOC 64
#define SCAN_THREADS 512
#define SLICE_BYTES (BPC*DLOC*4)             // 1024

__global__ __launch_bounds__(SCAN_THREADS, 1) __cluster_dims__(CLUSTER_C, 1, 1)
void scan_cluster_kernel(const float* __restrict__ Wp, const float* __restrict__ bp,
                         float* __restrict__ out)
{
    __shared__ __align__(16) float bel[2][CLUSTER_C][BPC][DLOC];  // 16 KB
    __shared__ __align__(16) float sp[BPC][8][DLOC];              // 8 KB
    __shared__ __align__(16) float stage[2][BPC][DLOC];           // 2 KB
    __shared__ __align__(8)  u64  sb[2][CLUSTER_C];               // slot barriers

    const int tid     = threadIdx.x;
    const int d_local = tid & 63;
    const int ksec    = tid >> 6;        // 0..7 == source rank this thread reads
    const int kbase   = ksec * 64;

    uint32_t rank;
    asm("mov.u32 %0, %%cluster_ctarank;" : "=r"(rank));
    const int cluster_id = blockIdx.x / CLUSTER_C;
    const int b0    = cluster_id * BPC;
    const int dglob = (int)rank * DLOC + d_local;

    // ---- Persistent Wp slice in registers ----
    float w[64];
    #pragma unroll
    for (int j = 0; j < 64; j++)
        w[j] = Wp[(size_t)(kbase + j) * DD + dglob];

    // ---- init belief buffer 0 + slot mbarriers ----
    for (int i = tid; i < CLUSTER_C * BPC * DLOC; i += SCAN_THREADS)
        (&bel[0][0][0][0])[i] = 0.0f;
    const uint32_t sb_base = (uint32_t)__cvta_generic_to_shared(&sb[0][0]);
    if (tid < 2 * CLUSTER_C) {
        const uint32_t mb = sb_base + tid * 8;
        asm volatile("mbarrier.init.shared.b64 [%0], 1;" :: "r"(mb) : "memory");
    }
    __syncthreads();

    // this thread's wait barrier addresses (slot = ksec), per buffer
    const uint32_t my_mb[2] = { sb_base + (uint32_t)ksec * 8,
                                sb_base + (uint32_t)(CLUSTER_C + ksec) * 8 };

    // ---- reducer state: threads 0..255 (warps 0..7), one per (batch,col) ----
    const int  rb     = ksec & 3;
    const bool is_red = (tid < 256);
    float bel_prev = 0.0f;
    float bpv = 0.0f;
    size_t io_base = 0;
    if (is_red) {
        bpv = bp[dglob];
        io_base = ((size_t)(b0 + rb) * TT) * DD + dglob;
    }

    // one cluster sync: all CTAs' bel[0] + barriers ready before any traffic
    asm volatile("barrier.cluster.arrive.aligned;" ::: "memory");
    asm volatile("barrier.cluster.wait.aligned;"   ::: "memory");

    int ph0 = 0, ph1 = 0;

    for (int t = 0; t < TT; t++) {
        const int cur = t & 1;
        const int nxt = cur ^ 1;

        // gate prefetch BEFORE the wait: DRAM latency hides under wait+matvec
        float evv = 0.f, lkv = 0.f, wrv = 0.f;
        if (is_red) {
            const size_t idx = io_base + (size_t)t * DD;
            evv = g_ev[idx];
            lkv = g_leak[idx];
            wrv = g_write[idx];
        }

        // ---- wait ONLY for my source slot (slice ksec of phase cur) ----
        if (t > 0) {
            const uint32_t mb = my_mb[cur];
            const int ph = cur ? ph1 : ph0;
            uint32_t done;
            asm volatile(
                "{\n\t.reg .pred p;\n\t"
                "mbarrier.try_wait.parity.acquire.cta.shared::cta.b64 p, [%1], %2;\n\t"
                "selp.b32 %0, 1, 0, p;\n\t}"
                : "=r"(done) : "r"(mb), "r"(ph) : "memory");
            if (!done) {
                asm volatile(
                    "{\n\t.reg .pred P1;\n\t"
                    "W%=:\n\t"
                    "mbarrier.try_wait.parity.acquire.cta.shared::cta.b64 P1, [%0], %1, 0x989680;\n\t"
                    "@P1 bra.uni D%=;\n\t"
                    "bra.uni W%=;\n\t"
                    "D%=:\n\t}"
                    :: "r"(mb), "r"(ph) : "memory");
            }
        }
        if (t > 0) { if (cur) ph1 ^= 1; else ph0 ^= 1; }

        // ---- matvec partials: 4-batch interleave (R8/R12-proven) ----
        const float4* bl0 = (const float4*)&bel[cur][ksec][0][0];
        const float4* bl1 = (const float4*)&bel[cur][ksec][1][0];
        const float4* bl2 = (const float4*)&bel[cur][ksec][2][0];
        const float4* bl3 = (const float4*)&bel[cur][ksec][3][0];
        float a0 = 0.f, a1 = 0.f, a2 = 0.f, a3 = 0.f;
        #pragma unroll
        for (int j4 = 0; j4 < 16; j4++) {
            const float4 v0 = bl0[j4];
            const float4 v1 = bl1[j4];
            const float4 v2 = bl2[j4];
            const float4 v3 = bl3[j4];
            a0 = fmaf(v0.x, w[4*j4+0], a0);
            a0 = fmaf(v0.y, w[4*j4+1], a0);
            a0 = fmaf(v0.z, w[4*j4+2], a0);
            a0 = fmaf(v0.w, w[4*j4+3], a0);
            a1 = fmaf(v1.x, w[4*j4+0], a1);
            a1 = fmaf(v1.y, w[4*j4+1], a1);
            a1 = fmaf(v1.z, w[4*j4+2], a1);
            a1 = fmaf(v1.w, w[4*j4+3], a1);
            a2 = fmaf(v2.x, w[4*j4+0], a2);
            a2 = fmaf(v2.y, w[4*j4+1], a2);
            a2 = fmaf(v2.z, w[4*j4+2], a2);
            a2 = fmaf(v2.w, w[4*j4+3], a2);
            a3 = fmaf(v3.x, w[4*j4+0], a3);
            a3 = fmaf(v3.y, w[4*j4+1], a3);
            a3 = fmaf(v3.z, w[4*j4+2], a3);
            a3 = fmaf(v3.w, w[4*j4+3], a3);
        }
        sp[0][ksec][d_local] = a0;
        sp[1][ksec][d_local] = a1;
        sp[2][ksec][d_local] = a2;
        sp[3][ksec][d_local] = a3;
        __syncthreads();   // sync#1: all partials visible to reducers

        if (is_red) {
            // ---- reduce + gates -> staging ----
            float s = 0.f;
            #pragma unroll
            for (int q = 0; q < 8; q++) s += sp[rb][q][d_local];
            const float cand = fast_tanh(s + bpv + evv);
            const float nb   = lkv * bel_prev + wrv * cand;
            bel_prev = nb;
            stage[cur][rb][d_local] = nb;
            // off-chain global store, issued before the barrier
            out[io_base + (size_t)t * DD] = nb;

            // sync#2: named barrier over the 256 reducer threads only
            asm volatile("bar.sync 1, 256;" ::: "memory");

            if (t < TT - 1) {
                // arm my local slot barriers for phase nxt: slot q expects 1KB
                if (tid < CLUSTER_C) {
                    const uint32_t mb_a =
                        sb_base + (uint32_t)(nxt * CLUSTER_C + tid) * 8;
                    asm volatile(
                        "mbarrier.arrive.expect_tx.shared.b64 _, [%0], %1;"
                        :: "r"(mb_a), "r"((uint32_t)SLICE_BYTES) : "memory");
                }
                // warp w's lane 0 sends MY slice to peer w, tagged to
                // the peer's slot barrier [nxt][my rank]
                if ((tid & 31) == 0) {
                    const int peer = tid >> 5;   // 0..7
                    asm volatile("fence.proxy.async.shared::cta;" ::: "memory");
                    const uint32_t mb_l =
                        sb_base + (uint32_t)(nxt * CLUSTER_C + (int)rank) * 8;
                    const uint32_t src =
                        (uint32_t)__cvta_generic_to_shared(&stage[cur][0][0]);
                    const uint32_t dst_l =
                        (uint32_t)__cvta_generic_to_shared(&bel[nxt][rank][0][0]);
                    uint32_t dst_r, mb_r;
                    asm("mapa.shared::cluster.u32 %0, %1, %2;"
                        : "=r"(dst_r) : "r"(dst_l), "r"(peer));
                    asm("mapa.shared::cluster.u32 %0, %1, %2;"
                        : "=r"(mb_r) : "r"(mb_l), "r"(peer));
                    asm volatile(
                        "cp.async.bulk.shared::cluster.shared::cta.mbarrier::complete_tx::bytes "
                        "[%0], [%1], %2, [%3];"
                        :: "r"(dst_r), "r"(src), "r"((uint32_t)SLICE_BYTES), "r"(mb_r)
                        : "memory");
                }
            }
        }
        // warps 8..15 fall through to their next slot wait; their sp
        // overwrite at t+1 is ordered by wait(t+1) <= senders' copies(t)
        // <= bar.sync1(t) <= reducers' sp reads(t).
    }
}

// ---------------------------------------------------------------------------
// Launch
// ---------------------------------------------------------------------------
extern "C" void kernel_launch(void* const* d_in, const int* in_sizes, int n_in,
                              void* d_out, int out_size)
{
    const float* evseq = (const float*)d_in[0];
    const float* We    = (const float*)d_in[1];
    const float* be    = (const float*)d_in[2];
    const float* Wp    = (const float*)d_in[3];
    const float* bp    = (const float*)d_in[4];
    const float* Wl    = (const float*)d_in[5];
    const float* bl    = (const float*)d_in[6];
    const float* Ww    = (const float*)d_in[7];
    const float* bw    = (const float*)d_in[8];
    float* out = (float*)d_out;

    float *p_ev, *p_leak, *p_write;
    cudaGetSymbolAddress((void**)&p_ev,    g_ev);
    cudaGetSymbolAddress((void**)&p_leak,  g_leak);
    cudaGetSymbolAddress((void**)&p_write, g_write);

    dim3 grid(MM / 128, DD / 128);
    dim3 blk(256);
    proj_gemm<0><<<grid, blk>>>(evseq, We, be, p_ev);
    proj_gemm<1><<<grid, blk>>>(evseq, Wl, bl, p_leak);
    proj_gemm<1><<<grid, blk>>>(evseq, Ww, bw, p_write);

    scan_cluster_kernel<<<NCLUST * CLUSTER_C, SCAN_THREADS>>>(Wp, bp, out);
}

// round 17
// speedup vs baseline: 1.5449x; 1.0532x over previous
#include <cuda_runtime.h>
#include <math.h>
#include <stdint.h>

#define BB 64
#define TT 512
#define DD 512
#define MM (BB*TT)   // 32768

typedef unsigned long long u64;

// Scratch for the precomputed projections (192 MB total)
__device__ float g_ev[MM*DD];
__device__ float g_leak[MM*DD];
__device__ float g_write[MM*DD];

// ---- packed fp32x2 helpers (Blackwell f32x2 pipe; exact IEEE fp32) ----
__device__ __forceinline__ u64 pack2(float lo, float hi) {
    u64 r; asm("mov.b64 %0, {%1, %2};" : "=l"(r) : "f"(lo), "f"(hi)); return r;
}
__device__ __forceinline__ void unpack2(u64 v, float& lo, float& hi) {
    asm("mov.b64 {%0, %1}, %2;" : "=f"(lo), "=f"(hi) : "l"(v));
}
__device__ __forceinline__ u64 ffma2(u64 a, u64 b, u64 c) {
    u64 d; asm("fma.rn.f32x2 %0, %1, %2, %3;" : "=l"(d) : "l"(a), "l"(b), "l"(c));
    return d;
}

// fast tanh: sign-safe, __expf-based (MUFU path), ~1e-6 rel error
__device__ __forceinline__ float fast_tanh(float x) {
    const float a = fabsf(x);
    const float t = __expf(-2.0f * a);
    const float r = __fdividef(1.0f - t, 1.0f + t);
    return copysignf(r, x);
}

// ---------------------------------------------------------------------------
// Kernel A: EXACT R12 winner. BM=128, BN=128, BK=16, 256 threads, 8x8 tile,
// f32x2 inner loop, k-major As, register-prefetch double buffering.
// ---------------------------------------------------------------------------
template<int ACT>
__global__ __launch_bounds__(256, 2)
void proj_gemm(const float* __restrict__ X, const float* __restrict__ W,
               const float* __restrict__ bias, float* __restrict__ Y)
{
    constexpr int BM = 128, BN = 128, BK = 16;
    __shared__ __align__(16) float As[BK*BM];   // [k][m]
    __shared__ __align__(16) float Bs[BK*BN];   // [k][n]

    const int tid = threadIdx.x;
    const int m0 = blockIdx.x * BM;
    const int n0 = blockIdx.y * BN;
    const int tx = tid & 15;
    const int ty = tid >> 4;

    const int arow = tid >> 2;
    const int acol = (tid & 3) * 4;
    const int brow = tid >> 5;
    const int bcol = (tid & 31) * 4;

    u64 acc2[8][4];
    #pragma unroll
    for (int i = 0; i < 8; i++)
        #pragma unroll
        for (int j = 0; j < 4; j++) acc2[i][j] = 0ULL;

    {
        float4 a0 = *(const float4*)&X[(size_t)(m0 + arow     ) * DD + acol];
        float4 a1 = *(const float4*)&X[(size_t)(m0 + arow + 64) * DD + acol];
        float4 b0 = *(const float4*)&W[(size_t)(brow    ) * DD + n0 + bcol];
        float4 b1 = *(const float4*)&W[(size_t)(brow + 8) * DD + n0 + bcol];
        As[(acol + 0) * BM + arow] = a0.x;
        As[(acol + 1) * BM + arow] = a0.y;
        As[(acol + 2) * BM + arow] = a0.z;
        As[(acol + 3) * BM + arow] = a0.w;
        As[(acol + 0) * BM + arow + 64] = a1.x;
        As[(acol + 1) * BM + arow + 64] = a1.y;
        As[(acol + 2) * BM + arow + 64] = a1.z;
        As[(acol + 3) * BM + arow + 64] = a1.w;
        *(float4*)&Bs[(brow    ) * BN + bcol] = b0;
        *(float4*)&Bs[(brow + 8) * BN + bcol] = b1;
    }
    __syncthreads();

    for (int k0 = 0; k0 < DD; k0 += BK) {
        const bool more = (k0 + BK < DD);
        float4 na0, na1, nb0, nb1;
        if (more) {
            na0 = *(const float4*)&X[(size_t)(m0 + arow     ) * DD + k0 + BK + acol];
            na1 = *(const float4*)&X[(size_t)(m0 + arow + 64) * DD + k0 + BK + acol];
            nb0 = *(const float4*)&W[(size_t)(k0 + BK + brow    ) * DD + n0 + bcol];
            nb1 = *(const float4*)&W[(size_t)(k0 + BK + brow + 8) * DD + n0 + bcol];
        }

        #pragma unroll
        for (int kk = 0; kk < BK; kk++) {
            float4 aA = *(const float4*)&As[kk * BM + ty * 8];
            float4 aB = *(const float4*)&As[kk * BM + ty * 8 + 4];
            ulonglong2 bp0 = *(const ulonglong2*)&Bs[kk * BN + tx * 8];
            ulonglong2 bp1 = *(const ulonglong2*)&Bs[kk * BN + tx * 8 + 4];
            u64 b2[4] = { bp0.x, bp0.y, bp1.x, bp1.y };
            float av[8] = { aA.x, aA.y, aA.z, aA.w, aB.x, aB.y, aB.z, aB.w };
            #pragma unroll
            for (int i = 0; i < 8; i++) {
                const u64 ap = pack2(av[i], av[i]);
                #pragma unroll
                for (int j = 0; j < 4; j++)
                    acc2[i][j] = ffma2(ap, b2[j], acc2[i][j]);
            }
        }

        if (more) {
            __syncthreads();
            As[(acol + 0) * BM + arow] = na0.x;
            As[(acol + 1) * BM + arow] = na0.y;
            As[(acol + 2) * BM + arow] = na0.z;
            As[(acol + 3) * BM + arow] = na0.w;
            As[(acol + 0) * BM + arow + 64] = na1.x;
            As[(acol + 1) * BM + arow + 64] = na1.y;
            As[(acol + 2) * BM + arow + 64] = na1.z;
            As[(acol + 3) * BM + arow + 64] = na1.w;
            *(float4*)&Bs[(brow    ) * BN + bcol] = nb0;
            *(float4*)&Bs[(brow + 8) * BN + bcol] = nb1;
            __syncthreads();
        }
    }

    #pragma unroll
    for (int i = 0; i < 8; i++) {
        const int m = m0 + ty * 8 + i;
        #pragma unroll
        for (int j = 0; j < 4; j++) {
            float lo, hi;
            unpack2(acc2[i][j], lo, hi);
            const int n = n0 + tx * 8 + 2 * j;
            float v0 = lo + bias[n];
            float v1 = hi + bias[n + 1];
            if (ACT == 1) {
                v0 = 1.0f / (1.0f + expf(-v0));
                v1 = 1.0f / (1.0f + expf(-v1));
            }
            Y[(size_t)m * DD + n]     = v0;
            Y[(size_t)m * DD + n + 1] = v1;
        }
    }
}

// ---------------------------------------------------------------------------
// Kernel B: cluster-resident scan (R12 base). CHANGE: the per-step broadcast
// is now per-warp chunked — each reducer warp, as soon as ITS 128B chunk of
// the belief slice is staged (syncwarp only, no bar.sync), has lanes 0..7
// send that chunk to all 8 peers. Receiver slot barriers still expect 1KB
// (8 warps x 128B), so the wait protocol is unchanged. This deletes
// bar.sync from the serial chain and overlaps warp-reduce skew with the
// DSMEM wire time. Arming moved off-chain to right after sync#1.
// ---------------------------------------------------------------------------
#define CLUSTER_C 8
#define NCLUST 16
#define BPC 4
#define DLOC 64
#define SCAN_THREADS 512
#define SLICE_BYTES (BPC*DLOC*4)             // 1024 (per-source per-step total)
#define CHUNK_BYTES 128                      // per-warp chunk (32 floats)

__global__ __launch_bounds__(SCAN_THREADS, 1) __cluster_dims__(CLUSTER_C, 1, 1)
void scan_cluster_kernel(const float* __restrict__ Wp, const float* __restrict__ bp,
                         float* __restrict__ out)
{
    __shared__ __align__(16) float bel[2][CLUSTER_C][BPC][DLOC];  // 16 KB
    __shared__ __align__(16) float sp[BPC][8][DLOC];              // 8 KB
    __shared__ __align__(16) float stage[2][BPC][DLOC];           // 2 KB
    __shared__ __align__(8)  u64  sb[2][CLUSTER_C];               // slot barriers

    const int tid     = threadIdx.x;
    const int d_local = tid & 63;
    const int ksec    = tid >> 6;        // 0..7 == source rank this thread reads
    const int kbase   = ksec * 64;

    uint32_t rank;
    asm("mov.u32 %0, %%cluster_ctarank;" : "=r"(rank));
    const int cluster_id = blockIdx.x / CLUSTER_C;
    const int b0    = cluster_id * BPC;
    const int dglob = (int)rank * DLOC + d_local;

    // ---- Persistent Wp slice in registers ----
    float w[64];
    #pragma unroll
    for (int j = 0; j < 64; j++)
        w[j] = Wp[(size_t)(kbase + j) * DD + dglob];

    // ---- init belief buffer 0 + slot mbarriers ----
    for (int i = tid; i < CLUSTER_C * BPC * DLOC; i += SCAN_THREADS)
        (&bel[0][0][0][0])[i] = 0.0f;
    const uint32_t sb_base = (uint32_t)__cvta_generic_to_shared(&sb[0][0]);
    if (tid < 2 * CLUSTER_C) {
        const uint32_t mb = sb_base + tid * 8;
        asm volatile("mbarrier.init.shared.b64 [%0], 1;" :: "r"(mb) : "memory");
    }
    __syncthreads();

    // this thread's wait barrier addresses (slot = ksec), per buffer
    const uint32_t my_mb[2] = { sb_base + (uint32_t)ksec * 8,
                                sb_base + (uint32_t)(CLUSTER_C + ksec) * 8 };

    // ---- reducer state: threads 0..255 (warps 0..7), one per (batch,col) ----
    const int  rb     = ksec & 3;                 // batch of this reducer
    const int  d0     = ((tid >> 5) & 1) * 32;    // warp's 32-col chunk base
    const bool is_red = (tid < 256);
    float bel_prev = 0.0f;
    float bpv = 0.0f;
    size_t io_base = 0;
    if (is_red) {
        bpv = bp[dglob];
        io_base = ((size_t)(b0 + rb) * TT) * DD + dglob;
    }

    // one cluster sync: all CTAs' bel[0] + barriers ready before any traffic
    asm volatile("barrier.cluster.arrive.aligned;" ::: "memory");
    asm volatile("barrier.cluster.wait.aligned;"   ::: "memory");

    int ph0 = 0, ph1 = 0;

    for (int t = 0; t < TT; t++) {
        const int cur = t & 1;
        const int nxt = cur ^ 1;

        // gate prefetch BEFORE the wait: DRAM latency hides under wait+matvec
        float evv = 0.f, lkv = 0.f, wrv = 0.f;
        if (is_red) {
            const size_t idx = io_base + (size_t)t * DD;
            evv = g_ev[idx];
            lkv = g_leak[idx];
            wrv = g_write[idx];
        }

        // ---- wait ONLY for my source slot (slice ksec of phase cur) ----
        if (t > 0) {
            const uint32_t mb = my_mb[cur];
            const int ph = cur ? ph1 : ph0;
            uint32_t done;
            asm volatile(
                "{\n\t.reg .pred p;\n\t"
                "mbarrier.try_wait.parity.acquire.cta.shared::cta.b64 p, [%1], %2;\n\t"
                "selp.b32 %0, 1, 0, p;\n\t}"
                : "=r"(done) : "r"(mb), "r"(ph) : "memory");
            if (!done) {
                asm volatile(
                    "{\n\t.reg .pred P1;\n\t"
                    "W%=:\n\t"
                    "mbarrier.try_wait.parity.acquire.cta.shared::cta.b64 P1, [%0], %1, 0x989680;\n\t"
                    "@P1 bra.uni D%=;\n\t"
                    "bra.uni W%=;\n\t"
                    "D%=:\n\t}"
                    :: "r"(mb), "r"(ph) : "memory");
            }
        }
        if (t > 0) { if (cur) ph1 ^= 1; else ph0 ^= 1; }

        // ---- matvec partials: 4-batch interleave (R8/R12-proven) ----
        const float4* bl0 = (const float4*)&bel[cur][ksec][0][0];
        const float4* bl1 = (const float4*)&bel[cur][ksec][1][0];
        const float4* bl2 = (const float4*)&bel[cur][ksec][2][0];
        const float4* bl3 = (const float4*)&bel[cur][ksec][3][0];
        float a0 = 0.f, a1 = 0.f, a2 = 0.f, a3 = 0.f;
        #pragma unroll
        for (int j4 = 0; j4 < 16; j4++) {
            const float4 v0 = bl0[j4];
            const float4 v1 = bl1[j4];
            const float4 v2 = bl2[j4];
            const float4 v3 = bl3[j4];
            a0 = fmaf(v0.x, w[4*j4+0], a0);
            a0 = fmaf(v0.y, w[4*j4+1], a0);
            a0 = fmaf(v0.z, w[4*j4+2], a0);
            a0 = fmaf(v0.w, w[4*j4+3], a0);
            a1 = fmaf(v1.x, w[4*j4+0], a1);
            a1 = fmaf(v1.y, w[4*j4+1], a1);
            a1 = fmaf(v1.z, w[4*j4+2], a1);
            a1 = fmaf(v1.w, w[4*j4+3], a1);
            a2 = fmaf(v2.x, w[4*j4+0], a2);
            a2 = fmaf(v2.y, w[4*j4+1], a2);
            a2 = fmaf(v2.z, w[4*j4+2], a2);
            a2 = fmaf(v2.w, w[4*j4+3], a2);
            a3 = fmaf(v3.x, w[4*j4+0], a3);
            a3 = fmaf(v3.y, w[4*j4+1], a3);
            a3 = fmaf(v3.z, w[4*j4+2], a3);
            a3 = fmaf(v3.w, w[4*j4+3], a3);
        }
        sp[0][ksec][d_local] = a0;
        sp[1][ksec][d_local] = a1;
        sp[2][ksec][d_local] = a2;
        sp[3][ksec][d_local] = a3;
        __syncthreads();   // sync#1: all partials visible to reducers

        if (is_red) {
            // arm my local slot barriers for phase nxt (off-chain; safe here:
            // all threads passed wait(t-1) on buffer nxt long before sync#1(t))
            if (t < TT - 1 && tid < CLUSTER_C) {
                const uint32_t mb_a =
                    sb_base + (uint32_t)(nxt * CLUSTER_C + tid) * 8;
                asm volatile(
                    "mbarrier.arrive.expect_tx.shared.b64 _, [%0], %1;"
                    :: "r"(mb_a), "r"((uint32_t)SLICE_BYTES) : "memory");
            }

            // ---- reduce + gates -> staging ----
            float s = 0.f;
            #pragma unroll
            for (int q = 0; q < 8; q++) s += sp[rb][q][d_local];
            const float cand = fast_tanh(s + bpv + evv);
            const float nb   = lkv * bel_prev + wrv * cand;
            bel_prev = nb;
            stage[cur][rb][d_local] = nb;
            __syncwarp();   // warp's 128B chunk fully staged

            // ---- per-warp chunked broadcast: lanes 0..7 -> 8 peers ----
            if (t < TT - 1) {
                asm volatile("fence.proxy.async.shared::cta;" ::: "memory");
                const int lane = tid & 31;
                if (lane < CLUSTER_C) {
                    const int peer = lane;
                    const uint32_t mb_l =
                        sb_base + (uint32_t)(nxt * CLUSTER_C + (int)rank) * 8;
                    const uint32_t src =
                        (uint32_t)__cvta_generic_to_shared(&stage[cur][rb][d0]);
                    const uint32_t dst_l =
                        (uint32_t)__cvta_generic_to_shared(&bel[nxt][rank][rb][d0]);
                    uint32_t dst_r, mb_r;
                    asm("mapa.shared::cluster.u32 %0, %1, %2;"
                        : "=r"(dst_r) : "r"(dst_l), "r"(peer));
                    asm("mapa.shared::cluster.u32 %0, %1, %2;"
                        : "=r"(mb_r) : "r"(mb_l), "r"(peer));
                    asm volatile(
                        "cp.async.bulk.shared::cluster.shared::cta.mbarrier::complete_tx::bytes "
                        "[%0], [%1], %2, [%3];"
                        :: "r"(dst_r), "r"(src), "r"((uint32_t)CHUNK_BYTES), "r"(mb_r)
                        : "memory");
                }
            }
            // off-chain global store (after sends)
            out[io_base + (size_t)t * DD] = nb;
        }
        // warps 8..15 fall through to their next slot wait; sp(t) reads by
        // reducers complete ~sync#1(t)+small, while any sp(t+1) overwrite
        // sits behind wait(t+1)+matvec(t+1) — ample ordering margin.
    }
}

// ---------------------------------------------------------------------------
// Launch
// ---------------------------------------------------------------------------
extern "C" void kernel_launch(void* const* d_in, const int* in_sizes, int n_in,
                              void* d_out, int out_size)
{
    const float* evseq = (const float*)d_in[0];
    const float* We    = (const float*)d_in[1];
    const float* be    = (const float*)d_in[2];
    const float* Wp    = (const float*)d_in[3];
    const float* bp    = (const float*)d_in[4];
    const float* Wl    = (const float*)d_in[5];
    const float* bl    = (const float*)d_in[6];
    const float* Ww    = (const float*)d_in[7];
    const float* bw    = (const float*)d_in[8];
    float* out = (float*)d_out;

    float *p_ev, *p_leak, *p_write;
    cudaGetSymbolAddress((void**)&p_ev,    g_ev);
    cudaGetSymbolAddress((void**)&p_leak,  g_leak);
    cudaGetSymbolAddress((void**)&p_write, g_write);

    dim3 grid(MM / 128, DD / 128);
    dim3 blk(256);
    proj_gemm<0><<<grid, blk>>>(evseq, We, be, p_ev);
    proj_gemm<1><<<grid, blk>>>(evseq, Wl, bl, p_leak);
    proj_gemm<1><<<grid, blk>>>(evseq, Ww, bw, p_write);

    scan_cluster_kernel<<<NCLUST * CLUSTER_C, SCAN_THREADS>>>(Wp, bp, out);
}